// round 3
// baseline (speedup 1.0000x reference)
#include <cuda_runtime.h>
#include <math.h>

// Problem constants (fixed shapes)
#define B_   2
#define T_   2048
#define D_   2048
#define H_   16
#define HD_  128
#define M_   (B_ * T_)      // 4096 rows
#define N1_  (3 * D_)       // 6144 qkv cols
#define SCALE_ 0.022097086912079612f   // 2048^-0.5  (note: D, not head_dim!)

// ---------------------------------------------------------------------------
// Scratch (device globals — no allocation allowed)
// ---------------------------------------------------------------------------
__device__ float g_qkv[(size_t)M_ * N1_];          // 100.7 MB
__device__ float g_q[(size_t)B_ * H_ * T_ * HD_];  // 33.5 MB
__device__ float g_k[(size_t)B_ * H_ * T_ * HD_];
__device__ float g_v[(size_t)B_ * H_ * T_ * HD_];
__device__ float g_attn[(size_t)M_ * D_];          // 33.5 MB

// ---------------------------------------------------------------------------
// Generic SGEMM: C[M,N] = A[M,K] @ W[N,K]^T + bias[N]
// 128x128 tile, BK=16, 256 threads, 8x8 per thread.
// ---------------------------------------------------------------------------
__global__ __launch_bounds__(256, 2) void sgemm_bias(
    const float* __restrict__ A, const float* __restrict__ W,
    const float* __restrict__ bias, float* __restrict__ C,
    int M, int N, int K)
{
    __shared__ __align__(16) float As[16][132];
    __shared__ __align__(16) float Bs[16][132];

    const int tid = threadIdx.x;
    const int bm = blockIdx.y * 128;
    const int bn = blockIdx.x * 128;
    const int ty = tid >> 4, tx = tid & 15;
    const int m0 = ty * 8, n0 = tx * 8;
    const int lrow = tid >> 2;           // 0..63
    const int lk   = (tid & 3) << 2;     // 0,4,8,12

    const float* Ap  = A + (size_t)(bm + lrow) * K + lk;
    const float* Ap2 = Ap + (size_t)64 * K;
    const float* Wp  = W + (size_t)(bn + lrow) * K + lk;
    const float* Wp2 = Wp + (size_t)64 * K;

    float acc[8][8];
#pragma unroll
    for (int i = 0; i < 8; i++)
#pragma unroll
        for (int j = 0; j < 8; j++) acc[i][j] = 0.0f;

    for (int k0 = 0; k0 < K; k0 += 16) {
        float4 a0 = *(const float4*)(Ap  + k0);
        float4 a1 = *(const float4*)(Ap2 + k0);
        float4 b0 = *(const float4*)(Wp  + k0);
        float4 b1 = *(const float4*)(Wp2 + k0);
        As[lk + 0][lrow] = a0.x; As[lk + 1][lrow] = a0.y;
        As[lk + 2][lrow] = a0.z; As[lk + 3][lrow] = a0.w;
        As[lk + 0][lrow + 64] = a1.x; As[lk + 1][lrow + 64] = a1.y;
        As[lk + 2][lrow + 64] = a1.z; As[lk + 3][lrow + 64] = a1.w;
        Bs[lk + 0][lrow] = b0.x; Bs[lk + 1][lrow] = b0.y;
        Bs[lk + 2][lrow] = b0.z; Bs[lk + 3][lrow] = b0.w;
        Bs[lk + 0][lrow + 64] = b1.x; Bs[lk + 1][lrow + 64] = b1.y;
        Bs[lk + 2][lrow + 64] = b1.z; Bs[lk + 3][lrow + 64] = b1.w;
        __syncthreads();

#pragma unroll
        for (int kk = 0; kk < 16; kk++) {
            float a[8], b[8];
            *(float4*)(a)     = *(const float4*)&As[kk][m0];
            *(float4*)(a + 4) = *(const float4*)&As[kk][m0 + 4];
            *(float4*)(b)     = *(const float4*)&Bs[kk][n0];
            *(float4*)(b + 4) = *(const float4*)&Bs[kk][n0 + 4];
#pragma unroll
            for (int i = 0; i < 8; i++)
#pragma unroll
                for (int j = 0; j < 8; j++)
                    acc[i][j] = fmaf(a[i], b[j], acc[i][j]);
        }
        __syncthreads();
    }

    float bv[8];
#pragma unroll
    for (int j = 0; j < 8; j++) bv[j] = bias[bn + n0 + j];

#pragma unroll
    for (int i = 0; i < 8; i++) {
        float* Cp = C + (size_t)(bm + m0 + i) * N + (bn + n0);
        float4 o0, o1;
        o0.x = acc[i][0] + bv[0]; o0.y = acc[i][1] + bv[1];
        o0.z = acc[i][2] + bv[2]; o0.w = acc[i][3] + bv[3];
        o1.x = acc[i][4] + bv[4]; o1.y = acc[i][5] + bv[5];
        o1.z = acc[i][6] + bv[6]; o1.w = acc[i][7] + bv[7];
        *(float4*)(Cp)     = o0;
        *(float4*)(Cp + 4) = o1;
    }
}

// ---------------------------------------------------------------------------
// RoPE + split qkv[B,T, H*3*hd] -> q/k/v [B,H,T,hd]  (rope on q,k)
// One thread per (b,h,t,i) with i in [0,64) handling the rotation pair.
// ---------------------------------------------------------------------------
__global__ __launch_bounds__(256) void rope_split(
    const float* __restrict__ qkv,
    float* __restrict__ qb, float* __restrict__ kb, float* __restrict__ vb)
{
    const int idx = blockIdx.x * blockDim.x + threadIdx.x;
    const int i  = idx & 63;
    const int t  = (idx >> 6) & (T_ - 1);
    const int h  = (idx >> 17) & (H_ - 1);
    const int b  = idx >> 21;
    const int bh = idx >> 17;   // b*16 + h

    const float* src = qkv + ((size_t)(b * T_ + t)) * N1_ + h * (3 * HD_);
    const float q1 = src[i],        q2 = src[64 + i];
    const float k1 = src[128 + i],  k2 = src[192 + i];
    const float v1 = src[256 + i],  v2 = src[320 + i];

    const float theta = powf(10000.0f, -(float)i * (1.0f / 64.0f));
    const float ang = (float)t * theta;
    const float cs = cosf(ang), sn = sinf(ang);

    const size_t dst = ((size_t)bh * T_ + t) * HD_ + i;
    qb[dst]      = q1 * cs - q2 * sn;
    qb[dst + 64] = q1 * sn + q2 * cs;
    kb[dst]      = k1 * cs - k2 * sn;
    kb[dst + 64] = k1 * sn + k2 * cs;
    vb[dst]      = v1;
    vb[dst + 64] = v2;
}

// ---------------------------------------------------------------------------
// Causal flash attention, fp32 SIMT.
// BM=128 q-rows x BN=64 k-cols per iteration, 256 threads.
// Q,K stored k-major (transposed) in smem for conflict-free float4 frags.
// O held in registers (8 rows x 8 dims per thread). Output written directly
// in [B,T,H*hd] layout (ready for the output projection).
// Dynamic smem layout (floats):
//   Qt [128][132]  @ 0       (16896)
//   Kt [128][68]   @ 16896   (8704)
//   Vs [64][128]   @ 25600   (8192)
//   Ps [128][68]   @ 33792   (8704)
//   m/l/c [128]x3  @ 42496   (384)      total 42880 floats = 171520 B
// ---------------------------------------------------------------------------
#define FLASH_SMEM_FLOATS 42880

__global__ __launch_bounds__(256, 1) void flash_kernel(
    const float* __restrict__ Qg, const float* __restrict__ Kg,
    const float* __restrict__ Vg, float* __restrict__ Og)
{
    extern __shared__ __align__(16) float sm[];
    float* Qt   = sm;
    float* Kt   = sm + 16896;
    float* Vs   = sm + 25600;
    float* Ps   = sm + 33792;
    float* mrow = sm + 42496;
    float* lrow = sm + 42624;
    float* crow = sm + 42752;

    const int tid = threadIdx.x;
    const int qt  = (int)gridDim.x - 1 - (int)blockIdx.x;  // heavy blocks first
    const int bh  = blockIdx.y;
    const int b   = bh >> 4, h = bh & 15;
    const size_t base = (size_t)bh * T_ * HD_;
    const float* Qb = Qg + base + (size_t)qt * 128 * HD_;

    // Load Q tile transposed: Qt[k][row]
    {
        const int row = tid >> 1;
        const int kq  = (tid & 1) << 2;
#pragma unroll
        for (int j = 0; j < 16; j++) {
            const int k = kq + j * 8;
            float4 vq = *(const float4*)(Qb + (size_t)row * HD_ + k);
            Qt[(k + 0) * 132 + row] = vq.x;
            Qt[(k + 1) * 132 + row] = vq.y;
            Qt[(k + 2) * 132 + row] = vq.z;
            Qt[(k + 3) * 132 + row] = vq.w;
        }
    }
    if (tid < 128) { mrow[tid] = -1e30f; lrow[tid] = 0.0f; }

    const int ty = tid >> 4, tx = tid & 15;
    const int r0 = ty * 8;   // 8 q-rows per thread
    const int c0 = tx * 4;   // 4 k-cols per thread (S phase)
    const int d0 = tx * 8;   // 8 head-dims per thread (PV phase)

    float o[8][8];
#pragma unroll
    for (int i = 0; i < 8; i++)
#pragma unroll
        for (int j = 0; j < 8; j++) o[i][j] = 0.0f;

    __syncthreads();

    const int ktmax = 2 * qt + 1;
    for (int kt = 0; kt <= ktmax; kt++) {
        const float* Kb = Kg + base + (size_t)kt * 64 * HD_;
        const float* Vb = Vg + base + (size_t)kt * 64 * HD_;

        // Load K tile transposed, V tile row-major
        {
            const int row = tid >> 2;
            const int kq  = (tid & 3) << 2;
#pragma unroll
            for (int j = 0; j < 8; j++) {
                const int k = kq + j * 16;
                float4 vk = *(const float4*)(Kb + (size_t)row * HD_ + k);
                Kt[(k + 0) * 68 + row] = vk.x;
                Kt[(k + 1) * 68 + row] = vk.y;
                Kt[(k + 2) * 68 + row] = vk.z;
                Kt[(k + 3) * 68 + row] = vk.w;
            }
#pragma unroll
            for (int j = 0; j < 8; j++) {
                const int e = tid + j * 256;
                ((float4*)Vs)[e] = ((const float4*)Vb)[e];
            }
        }
        __syncthreads();

        // ---- S = Q @ K^T ----
        float s[8][4];
#pragma unroll
        for (int i = 0; i < 8; i++)
#pragma unroll
            for (int j = 0; j < 4; j++) s[i][j] = 0.0f;

#pragma unroll 2
        for (int kk = 0; kk < 128; kk++) {
            const float4 q0 = *(const float4*)&Qt[kk * 132 + r0];
            const float4 q1 = *(const float4*)&Qt[kk * 132 + r0 + 4];
            const float4 kf = *(const float4*)&Kt[kk * 68 + c0];
            const float qa[8] = {q0.x, q0.y, q0.z, q0.w, q1.x, q1.y, q1.z, q1.w};
            const float kb4[4] = {kf.x, kf.y, kf.z, kf.w};
#pragma unroll
            for (int i = 0; i < 8; i++)
#pragma unroll
                for (int j = 0; j < 4; j++)
                    s[i][j] = fmaf(qa[i], kb4[j], s[i][j]);
        }

        // ---- scale + causal mask + stage to smem ----
        const bool diag = (kt >= 2 * qt);
        const int kbase = kt * 64 + c0;
#pragma unroll
        for (int i = 0; i < 8; i++) {
            const int qglob = qt * 128 + r0 + i;
            float4 sv;
            sv.x = s[i][0] * SCALE_;
            sv.y = s[i][1] * SCALE_;
            sv.z = s[i][2] * SCALE_;
            sv.w = s[i][3] * SCALE_;
            if (diag) {
                if (kbase + 0 > qglob) sv.x = -1e30f;
                if (kbase + 1 > qglob) sv.y = -1e30f;
                if (kbase + 2 > qglob) sv.z = -1e30f;
                if (kbase + 3 > qglob) sv.w = -1e30f;
            }
            *(float4*)&Ps[(r0 + i) * 68 + c0] = sv;
        }
        __syncthreads();

        // ---- online softmax (one thread per row) ----
        if (tid < 128) {
            float* pr = Ps + tid * 68;
            float mt = -1e30f;
#pragma unroll 4
            for (int j = 0; j < 64; j++) mt = fmaxf(mt, pr[j]);
            const float mold = mrow[tid];
            const float mn = fmaxf(mold, mt);
            const float c = expf(mold - mn);
            float sum = 0.0f;
#pragma unroll 4
            for (int j = 0; j < 64; j++) {
                const float p = expf(pr[j] - mn);
                pr[j] = p;
                sum += p;
            }
            lrow[tid] = lrow[tid] * c + sum;
            mrow[tid] = mn;
            crow[tid] = c;
        }
        __syncthreads();

        // ---- O = O * c + P @ V ----
#pragma unroll
        for (int i = 0; i < 8; i++) {
            const float c = crow[r0 + i];
#pragma unroll
            for (int j = 0; j < 8; j++) o[i][j] *= c;
        }
#pragma unroll 2
        for (int j = 0; j < 64; j++) {
            const float4 v0 = *(const float4*)&Vs[j * 128 + d0];
            const float4 v1 = *(const float4*)&Vs[j * 128 + d0 + 4];
#pragma unroll
            for (int i = 0; i < 8; i++) {
                const float p = Ps[(r0 + i) * 68 + j];
                o[i][0] = fmaf(p, v0.x, o[i][0]);
                o[i][1] = fmaf(p, v0.y, o[i][1]);
                o[i][2] = fmaf(p, v0.z, o[i][2]);
                o[i][3] = fmaf(p, v0.w, o[i][3]);
                o[i][4] = fmaf(p, v1.x, o[i][4]);
                o[i][5] = fmaf(p, v1.y, o[i][5]);
                o[i][6] = fmaf(p, v1.z, o[i][6]);
                o[i][7] = fmaf(p, v1.w, o[i][7]);
            }
        }
        __syncthreads();
    }

    // ---- normalize + write out in [B, T, H*hd] layout ----
#pragma unroll
    for (int i = 0; i < 8; i++) {
        const float inv = 1.0f / lrow[r0 + i];
        const int qglob = qt * 128 + r0 + i;
        float* outp = Og + ((size_t)(b * T_ + qglob)) * D_ + h * HD_ + d0;
        float4 w0, w1;
        w0.x = o[i][0] * inv; w0.y = o[i][1] * inv;
        w0.z = o[i][2] * inv; w0.w = o[i][3] * inv;
        w1.x = o[i][4] * inv; w1.y = o[i][5] * inv;
        w1.z = o[i][6] * inv; w1.w = o[i][7] * inv;
        *(float4*)(outp)     = w0;
        *(float4*)(outp + 4) = w1;
    }
}

// ---------------------------------------------------------------------------
// kernel_launch
// ---------------------------------------------------------------------------
extern "C" void kernel_launch(void* const* d_in, const int* in_sizes, int n_in,
                              void* d_out, int out_size)
{
    const float* x     = (const float*)d_in[0];
    const float* w_qkv = (const float*)d_in[1];
    const float* b_qkv = (const float*)d_in[2];
    const float* w_out = (const float*)d_in[3];
    const float* b_out = (const float*)d_in[4];
    float* out = (float*)d_out;

    float *qkv, *q, *k, *v, *attn;
    cudaGetSymbolAddress((void**)&qkv,  g_qkv);
    cudaGetSymbolAddress((void**)&q,    g_q);
    cudaGetSymbolAddress((void**)&k,    g_k);
    cudaGetSymbolAddress((void**)&v,    g_v);
    cudaGetSymbolAddress((void**)&attn, g_attn);

    cudaFuncSetAttribute(flash_kernel,
                         cudaFuncAttributeMaxDynamicSharedMemorySize,
                         FLASH_SMEM_FLOATS * (int)sizeof(float));

    // 1) qkv = x @ w_qkv^T + b_qkv
    sgemm_bias<<<dim3(N1_ / 128, M_ / 128), 256>>>(x, w_qkv, b_qkv, qkv,
                                                   M_, N1_, D_);
    // 2) RoPE + head split
    rope_split<<<(B_ * H_ * T_ * 64) / 256, 256>>>(qkv, q, k, v);
    // 3) causal flash attention
    flash_kernel<<<dim3(T_ / 128, B_ * H_), 256,
                   FLASH_SMEM_FLOATS * (int)sizeof(float)>>>(q, k, v, attn);
    // 4) out = attn @ w_out^T + b_out
    sgemm_bias<<<dim3(D_ / 128, M_ / 128), 256>>>(attn, w_out, b_out, out,
                                                  M_, D_, D_);
}

// round 6
// speedup vs baseline: 1.8976x; 1.8976x over previous
#include <cuda_runtime.h>
#include <cuda_bf16.h>
#include <cstdint>
#include <math.h>

// Problem constants (fixed shapes)
#define B_   2
#define T_   2048
#define D_   2048
#define H_   16
#define HD_  128
#define M_   (B_ * T_)      // 4096 rows
#define N1_  (3 * D_)       // 6144 qkv cols
#define SCALE_ 0.022097086912079612f   // 2048^-0.5  (D, not head_dim!)

// ---------------------------------------------------------------------------
// Scratch (device globals — no allocation allowed)
// ---------------------------------------------------------------------------
__device__ float g_qkv[(size_t)M_ * N1_];          // 100.7 MB
__device__ float g_q[(size_t)B_ * H_ * T_ * HD_];  // 33.5 MB
__device__ float g_k[(size_t)B_ * H_ * T_ * HD_];
__device__ float g_v[(size_t)B_ * H_ * T_ * HD_];
__device__ float g_attn[(size_t)M_ * D_];          // 33.5 MB
// bf16 split operands for tensor-core GEMMs
__device__ __nv_bfloat16 g_xh[(size_t)M_ * D_];
__device__ __nv_bfloat16 g_xl[(size_t)M_ * D_];
__device__ __nv_bfloat16 g_wqh[(size_t)N1_ * D_];
__device__ __nv_bfloat16 g_wql[(size_t)N1_ * D_];
__device__ __nv_bfloat16 g_ah[(size_t)M_ * D_];
__device__ __nv_bfloat16 g_al[(size_t)M_ * D_];
__device__ __nv_bfloat16 g_wh[(size_t)D_ * D_];
__device__ __nv_bfloat16 g_wl[(size_t)D_ * D_];

// ---------------------------------------------------------------------------
// PTX helpers (family-portable only: ldmatrix / mma.sync / cp.async)
// ---------------------------------------------------------------------------
__device__ __forceinline__ uint32_t smem_to_u32(const void* p) {
    uint32_t a;
    asm("{ .reg .u64 t; cvta.to.shared.u64 t, %1; cvt.u32.u64 %0, t; }"
        : "=r"(a) : "l"(p));
    return a;
}
#define SMEM_SWIZZLE_128B(off) ((off) ^ (((off) >> 3) & 0x70))

#define CP_ASYNC16(dst, src) \
    asm volatile("cp.async.cg.shared.global [%0], [%1], 16;" \
                 :: "r"((uint32_t)(dst)), "l"(src))
#define CP_ASYNC_COMMIT() asm volatile("cp.async.commit_group;" ::: "memory")

__device__ __forceinline__ void ldsm4(uint32_t* r, uint32_t addr) {
    asm volatile("ldmatrix.sync.aligned.m8n8.x4.shared.b16 {%0,%1,%2,%3}, [%4];"
                 : "=r"(r[0]), "=r"(r[1]), "=r"(r[2]), "=r"(r[3]) : "r"(addr));
}

__device__ __forceinline__ void mma16816(float* c, const uint32_t* a,
                                         uint32_t b0, uint32_t b1) {
    asm volatile(
        "mma.sync.aligned.m16n8k16.row.col.f32.bf16.bf16.f32 "
        "{%0,%1,%2,%3}, {%4,%5,%6,%7}, {%8,%9}, {%0,%1,%2,%3};"
        : "+f"(c[0]), "+f"(c[1]), "+f"(c[2]), "+f"(c[3])
        : "r"(a[0]), "r"(a[1]), "r"(a[2]), "r"(a[3]), "r"(b0), "r"(b1));
}

// ---------------------------------------------------------------------------
// fp32 -> (bf16 hi, bf16 lo) split, vectorized
// ---------------------------------------------------------------------------
__global__ __launch_bounds__(256) void split_bf16(
    const float* __restrict__ src, __nv_bfloat16* __restrict__ hi,
    __nv_bfloat16* __restrict__ lo)
{
    const int i = blockIdx.x * 256 + threadIdx.x;   // float4 index
    float4 v = ((const float4*)src)[i];
    __nv_bfloat16 h0 = __float2bfloat16(v.x);
    __nv_bfloat16 h1 = __float2bfloat16(v.y);
    __nv_bfloat16 h2 = __float2bfloat16(v.z);
    __nv_bfloat16 h3 = __float2bfloat16(v.w);
    __nv_bfloat16 l0 = __float2bfloat16(v.x - __bfloat162float(h0));
    __nv_bfloat16 l1 = __float2bfloat16(v.y - __bfloat162float(h1));
    __nv_bfloat16 l2 = __float2bfloat16(v.z - __bfloat162float(h2));
    __nv_bfloat16 l3 = __float2bfloat16(v.w - __bfloat162float(h3));
    __nv_bfloat162 hp0(h0, h1), hp1(h2, h3), lp0(l0, l1), lp1(l2, l3);
    ((uint2*)hi)[i] = make_uint2(*(uint32_t*)&hp0, *(uint32_t*)&hp1);
    ((uint2*)lo)[i] = make_uint2(*(uint32_t*)&lp0, *(uint32_t*)&lp1);
}

// ---------------------------------------------------------------------------
// HMMA GEMM: C[M,N] = A[M,K] @ W[N,K]^T + bias   (bf16 3-term split)
// CTA 128x128, BK=64, 8 warps (2 m x 4 n), warp tile 64x32.
// SMEM per buffer (64KB): Ah 16K | Al 16K | Bh 16K | Bl 16K,
// each tile 128 rows x 64 bf16 (128B rows), SW128 swizzle. Double buffered.
// ---------------------------------------------------------------------------
#define GEMM_SMEM_BYTES (131072 + 1024)

__device__ __forceinline__ void load_chunk(
    const __nv_bfloat16* Ah, const __nv_bfloat16* Al,
    const __nv_bfloat16* Bh, const __nv_bfloat16* Bl,
    int bm, int bn, int K, int k0, uint32_t dbase, int tid)
{
#pragma unroll
    for (int i = 0; i < 16; i++) {
        const int idx = tid + i * 256;
        const int t   = idx >> 10;           // tile 0..3
        const int r   = (idx >> 3) & 127;    // row within tile
        const int c16 = idx & 7;             // 16B segment within 128B row
        const __nv_bfloat16* sp;
        int row;
        if (t == 0)      { sp = Ah; row = bm + r; }
        else if (t == 1) { sp = Al; row = bm + r; }
        else if (t == 2) { sp = Bh; row = bn + r; }
        else             { sp = Bl; row = bn + r; }
        const char* src = (const char*)sp +
            (((size_t)row * K + k0) << 1) + (c16 << 4);
        const uint32_t off = (r << 7) + (c16 << 4);
        const uint32_t dst = dbase + (t << 14) + SMEM_SWIZZLE_128B(off);
        CP_ASYNC16(dst, src);
    }
    CP_ASYNC_COMMIT();
}

__global__ __launch_bounds__(256, 1) void gemm_hmma(
    const __nv_bfloat16* __restrict__ Ah, const __nv_bfloat16* __restrict__ Al,
    const __nv_bfloat16* __restrict__ Bh, const __nv_bfloat16* __restrict__ Bl,
    const float* __restrict__ bias, float* __restrict__ C,
    int M, int N, int K)
{
    extern __shared__ __align__(16) char smem[];
    const uint32_t data0 = (smem_to_u32(smem) + 1023) & ~1023u;

    const int tid  = threadIdx.x;
    const int lane = tid & 31;
    const int wid  = tid >> 5;
    const int warp_m = wid >> 2;       // 0..1
    const int warp_n = wid & 3;        // 0..3
    const int bm = blockIdx.y * 128;
    const int bn = blockIdx.x * 128;

    // per-lane ldmatrix source coordinates
    const uint32_t a_row = warp_m * 64 + (lane & 15);
    const uint32_t a_kb  = (uint32_t)(lane >> 4) << 4;
    const uint32_t b_row = warp_n * 32 + (lane & 7) + (((uint32_t)lane >> 4) << 3);
    const uint32_t b_kb  = (((uint32_t)lane >> 3) & 1) << 4;

    float acc[4][4][4];
#pragma unroll
    for (int mt = 0; mt < 4; mt++)
#pragma unroll
        for (int nt = 0; nt < 4; nt++)
#pragma unroll
            for (int r = 0; r < 4; r++) acc[mt][nt][r] = 0.0f;

    const int nchunks = K >> 6;

    load_chunk(Ah, Al, Bh, Bl, bm, bn, K, 0, data0, tid);

    for (int c = 0; c < nchunks; c++) {
        if (c + 1 < nchunks) {
            load_chunk(Ah, Al, Bh, Bl, bm, bn, K, (c + 1) << 6,
                       data0 + ((c + 1) & 1) * 65536, tid);
            asm volatile("cp.async.wait_group 1;" ::: "memory");
        } else {
            asm volatile("cp.async.wait_group 0;" ::: "memory");
        }
        __syncthreads();

        const uint32_t dbase = data0 + (c & 1) * 65536;
        const uint32_t sAh = dbase;
        const uint32_t sAl = dbase + 16384;
        const uint32_t sBh = dbase + 32768;
        const uint32_t sBl = dbase + 49152;

#pragma unroll
        for (int ks = 0; ks < 4; ks++) {
            const uint32_t kbyte = (uint32_t)ks << 5;   // 32B per k16 step

            uint32_t af_h[4][4], af_l[4][4];
#pragma unroll
            for (int mt = 0; mt < 4; mt++) {
                const uint32_t off = ((a_row + mt * 16) << 7) + kbyte + a_kb;
                const uint32_t sw = SMEM_SWIZZLE_128B(off);
                ldsm4(af_h[mt], sAh + sw);
                ldsm4(af_l[mt], sAl + sw);
            }
            uint32_t bf_h[2][4], bf_l[2][4];
#pragma unroll
            for (int ng = 0; ng < 2; ng++) {
                const uint32_t off = ((b_row + ng * 16) << 7) + kbyte + b_kb;
                const uint32_t sw = SMEM_SWIZZLE_128B(off);
                ldsm4(bf_h[ng], sBh + sw);
                ldsm4(bf_l[ng], sBl + sw);
            }
#pragma unroll
            for (int mt = 0; mt < 4; mt++) {
#pragma unroll
                for (int nt = 0; nt < 4; nt++) {
                    const int ng = nt >> 1, lo = (nt & 1) * 2;
                    mma16816(acc[mt][nt], af_h[mt], bf_h[ng][lo], bf_h[ng][lo + 1]);
                    mma16816(acc[mt][nt], af_h[mt], bf_l[ng][lo], bf_l[ng][lo + 1]);
                    mma16816(acc[mt][nt], af_l[mt], bf_h[ng][lo], bf_h[ng][lo + 1]);
                }
            }
        }
        __syncthreads();
    }

    // Epilogue: C-fragment rows (lane>>2, +8), cols 2*(lane&3)+{0,1}
    const int gm0 = bm + warp_m * 64 + (lane >> 2);
    const int gn0 = bn + warp_n * 32 + (lane & 3) * 2;
#pragma unroll
    for (int mt = 0; mt < 4; mt++) {
#pragma unroll
        for (int nt = 0; nt < 4; nt++) {
            const int gm = gm0 + mt * 16;
            const int gn = gn0 + nt * 8;
            const float b0 = bias[gn], b1 = bias[gn + 1];
            float2 v0 = make_float2(acc[mt][nt][0] + b0, acc[mt][nt][1] + b1);
            float2 v1 = make_float2(acc[mt][nt][2] + b0, acc[mt][nt][3] + b1);
            *(float2*)&C[(size_t)gm * N + gn]       = v0;
            *(float2*)&C[(size_t)(gm + 8) * N + gn] = v1;
        }
    }
}

// ---------------------------------------------------------------------------
// RoPE + split qkv[B,T, H*3*hd] -> q/k/v [B,H,T,hd]  (rope on q,k)
// ---------------------------------------------------------------------------
__global__ __launch_bounds__(256) void rope_split(
    const float* __restrict__ qkv,
    float* __restrict__ qb, float* __restrict__ kb, float* __restrict__ vb)
{
    const int idx = blockIdx.x * blockDim.x + threadIdx.x;
    const int i  = idx & 63;
    const int t  = (idx >> 6) & (T_ - 1);
    const int h  = (idx >> 17) & (H_ - 1);
    const int b  = idx >> 21;
    const int bh = idx >> 17;   // b*16 + h

    const float* src = qkv + ((size_t)(b * T_ + t)) * N1_ + h * (3 * HD_);
    const float q1 = src[i],        q2 = src[64 + i];
    const float k1 = src[128 + i],  k2 = src[192 + i];
    const float v1 = src[256 + i],  v2 = src[320 + i];

    const float theta = powf(10000.0f, -(float)i * (1.0f / 64.0f));
    const float ang = (float)t * theta;
    const float cs = cosf(ang), sn = sinf(ang);

    const size_t dst = ((size_t)bh * T_ + t) * HD_ + i;
    qb[dst]      = q1 * cs - q2 * sn;
    qb[dst + 64] = q1 * sn + q2 * cs;
    kb[dst]      = k1 * cs - k2 * sn;
    kb[dst + 64] = k1 * sn + k2 * cs;
    vb[dst]      = v1;
    vb[dst + 64] = v2;
}

// ---------------------------------------------------------------------------
// Causal flash attention, fp32 SIMT (unchanged from R3 passing version).
// ---------------------------------------------------------------------------
#define FLASH_SMEM_FLOATS 42880

__global__ __launch_bounds__(256, 1) void flash_kernel(
    const float* __restrict__ Qg, const float* __restrict__ Kg,
    const float* __restrict__ Vg, float* __restrict__ Og)
{
    extern __shared__ __align__(16) float sm[];
    float* Qt   = sm;
    float* Kt   = sm + 16896;
    float* Vs   = sm + 25600;
    float* Ps   = sm + 33792;
    float* mrow = sm + 42496;
    float* lrow = sm + 42624;
    float* crow = sm + 42752;

    const int tid = threadIdx.x;
    const int qt  = (int)gridDim.x - 1 - (int)blockIdx.x;  // heavy blocks first
    const int bh  = blockIdx.y;
    const int b   = bh >> 4, h = bh & 15;
    const size_t base = (size_t)bh * T_ * HD_;
    const float* Qb = Qg + base + (size_t)qt * 128 * HD_;

    {
        const int row = tid >> 1;
        const int kq  = (tid & 1) << 2;
#pragma unroll
        for (int j = 0; j < 16; j++) {
            const int k = kq + j * 8;
            float4 vq = *(const float4*)(Qb + (size_t)row * HD_ + k);
            Qt[(k + 0) * 132 + row] = vq.x;
            Qt[(k + 1) * 132 + row] = vq.y;
            Qt[(k + 2) * 132 + row] = vq.z;
            Qt[(k + 3) * 132 + row] = vq.w;
        }
    }
    if (tid < 128) { mrow[tid] = -1e30f; lrow[tid] = 0.0f; }

    const int ty = tid >> 4, tx = tid & 15;
    const int r0 = ty * 8;
    const int c0 = tx * 4;
    const int d0 = tx * 8;

    float o[8][8];
#pragma unroll
    for (int i = 0; i < 8; i++)
#pragma unroll
        for (int j = 0; j < 8; j++) o[i][j] = 0.0f;

    __syncthreads();

    const int ktmax = 2 * qt + 1;
    for (int kt = 0; kt <= ktmax; kt++) {
        const float* Kb = Kg + base + (size_t)kt * 64 * HD_;
        const float* Vb = Vg + base + (size_t)kt * 64 * HD_;

        {
            const int row = tid >> 2;
            const int kq  = (tid & 3) << 2;
#pragma unroll
            for (int j = 0; j < 8; j++) {
                const int k = kq + j * 16;
                float4 vk = *(const float4*)(Kb + (size_t)row * HD_ + k);
                Kt[(k + 0) * 68 + row] = vk.x;
                Kt[(k + 1) * 68 + row] = vk.y;
                Kt[(k + 2) * 68 + row] = vk.z;
                Kt[(k + 3) * 68 + row] = vk.w;
            }
#pragma unroll
            for (int j = 0; j < 8; j++) {
                const int e = tid + j * 256;
                ((float4*)Vs)[e] = ((const float4*)Vb)[e];
            }
        }
        __syncthreads();

        float s[8][4];
#pragma unroll
        for (int i = 0; i < 8; i++)
#pragma unroll
            for (int j = 0; j < 4; j++) s[i][j] = 0.0f;

#pragma unroll 2
        for (int kk = 0; kk < 128; kk++) {
            const float4 q0 = *(const float4*)&Qt[kk * 132 + r0];
            const float4 q1 = *(const float4*)&Qt[kk * 132 + r0 + 4];
            const float4 kf = *(const float4*)&Kt[kk * 68 + c0];
            const float qa[8] = {q0.x, q0.y, q0.z, q0.w, q1.x, q1.y, q1.z, q1.w};
            const float kb4[4] = {kf.x, kf.y, kf.z, kf.w};
#pragma unroll
            for (int i = 0; i < 8; i++)
#pragma unroll
                for (int j = 0; j < 4; j++)
                    s[i][j] = fmaf(qa[i], kb4[j], s[i][j]);
        }

        const bool diag = (kt >= 2 * qt);
        const int kbase = kt * 64 + c0;
#pragma unroll
        for (int i = 0; i < 8; i++) {
            const int qglob = qt * 128 + r0 + i;
            float4 sv;
            sv.x = s[i][0] * SCALE_;
            sv.y = s[i][1] * SCALE_;
            sv.z = s[i][2] * SCALE_;
            sv.w = s[i][3] * SCALE_;
            if (diag) {
                if (kbase + 0 > qglob) sv.x = -1e30f;
                if (kbase + 1 > qglob) sv.y = -1e30f;
                if (kbase + 2 > qglob) sv.z = -1e30f;
                if (kbase + 3 > qglob) sv.w = -1e30f;
            }
            *(float4*)&Ps[(r0 + i) * 68 + c0] = sv;
        }
        __syncthreads();

        if (tid < 128) {
            float* pr = Ps + tid * 68;
            float mt = -1e30f;
#pragma unroll 4
            for (int j = 0; j < 64; j++) mt = fmaxf(mt, pr[j]);
            const float mold = mrow[tid];
            const float mn = fmaxf(mold, mt);
            const float c = expf(mold - mn);
            float sum = 0.0f;
#pragma unroll 4
            for (int j = 0; j < 64; j++) {
                const float p = expf(pr[j] - mn);
                pr[j] = p;
                sum += p;
            }
            lrow[tid] = lrow[tid] * c + sum;
            mrow[tid] = mn;
            crow[tid] = c;
        }
        __syncthreads();

#pragma unroll
        for (int i = 0; i < 8; i++) {
            const float c = crow[r0 + i];
#pragma unroll
            for (int j = 0; j < 8; j++) o[i][j] *= c;
        }
#pragma unroll 2
        for (int j = 0; j < 64; j++) {
            const float4 v0 = *(const float4*)&Vs[j * 128 + d0];
            const float4 v1 = *(const float4*)&Vs[j * 128 + d0 + 4];
#pragma unroll
            for (int i = 0; i < 8; i++) {
                const float p = Ps[(r0 + i) * 68 + j];
                o[i][0] = fmaf(p, v0.x, o[i][0]);
                o[i][1] = fmaf(p, v0.y, o[i][1]);
                o[i][2] = fmaf(p, v0.z, o[i][2]);
                o[i][3] = fmaf(p, v0.w, o[i][3]);
                o[i][4] = fmaf(p, v1.x, o[i][4]);
                o[i][5] = fmaf(p, v1.y, o[i][5]);
                o[i][6] = fmaf(p, v1.z, o[i][6]);
                o[i][7] = fmaf(p, v1.w, o[i][7]);
            }
        }
        __syncthreads();
    }

#pragma unroll
    for (int i = 0; i < 8; i++) {
        const float inv = 1.0f / lrow[r0 + i];
        const int qglob = qt * 128 + r0 + i;
        float* outp = Og + ((size_t)(b * T_ + qglob)) * D_ + h * HD_ + d0;
        float4 w0, w1;
        w0.x = o[i][0] * inv; w0.y = o[i][1] * inv;
        w0.z = o[i][2] * inv; w0.w = o[i][3] * inv;
        w1.x = o[i][4] * inv; w1.y = o[i][5] * inv;
        w1.z = o[i][6] * inv; w1.w = o[i][7] * inv;
        *(float4*)(outp)     = w0;
        *(float4*)(outp + 4) = w1;
    }
}

// ---------------------------------------------------------------------------
// kernel_launch
// ---------------------------------------------------------------------------
extern "C" void kernel_launch(void* const* d_in, const int* in_sizes, int n_in,
                              void* d_out, int out_size)
{
    const float* x     = (const float*)d_in[0];
    const float* w_qkv = (const float*)d_in[1];
    const float* b_qkv = (const float*)d_in[2];
    const float* w_out = (const float*)d_in[3];
    const float* b_out = (const float*)d_in[4];
    float* out = (float*)d_out;

    float *qkv, *q, *k, *v, *attn;
    cudaGetSymbolAddress((void**)&qkv,  g_qkv);
    cudaGetSymbolAddress((void**)&q,    g_q);
    cudaGetSymbolAddress((void**)&k,    g_k);
    cudaGetSymbolAddress((void**)&v,    g_v);
    cudaGetSymbolAddress((void**)&attn, g_attn);
    __nv_bfloat16 *xh, *xl, *wqh, *wql, *ah, *al, *wh, *wl;
    cudaGetSymbolAddress((void**)&xh,  g_xh);
    cudaGetSymbolAddress((void**)&xl,  g_xl);
    cudaGetSymbolAddress((void**)&wqh, g_wqh);
    cudaGetSymbolAddress((void**)&wql, g_wql);
    cudaGetSymbolAddress((void**)&ah,  g_ah);
    cudaGetSymbolAddress((void**)&al,  g_al);
    cudaGetSymbolAddress((void**)&wh,  g_wh);
    cudaGetSymbolAddress((void**)&wl,  g_wl);

    cudaFuncSetAttribute(flash_kernel,
                         cudaFuncAttributeMaxDynamicSharedMemorySize,
                         FLASH_SMEM_FLOATS * (int)sizeof(float));
    cudaFuncSetAttribute(gemm_hmma,
                         cudaFuncAttributeMaxDynamicSharedMemorySize,
                         GEMM_SMEM_BYTES);

    // 0) split inputs/weights into bf16 hi/lo
    split_bf16<<<((size_t)M_ * D_) / 1024, 256>>>(x, xh, xl);
    split_bf16<<<((size_t)N1_ * D_) / 1024, 256>>>(w_qkv, wqh, wql);
    // 1) qkv = x @ w_qkv^T + b_qkv   (HMMA, bf16 3-term)
    gemm_hmma<<<dim3(N1_ / 128, M_ / 128), 256, GEMM_SMEM_BYTES>>>(
        xh, xl, wqh, wql, b_qkv, qkv, M_, N1_, D_);
    // 2) RoPE + head split
    rope_split<<<(B_ * H_ * T_ * 64) / 256, 256>>>(qkv, q, k, v);
    // 3) causal flash attention
    flash_kernel<<<dim3(T_ / 128, B_ * H_), 256,
                   FLASH_SMEM_FLOATS * (int)sizeof(float)>>>(q, k, v, attn);
    // 4) split attn / w_out, then out = attn @ w_out^T + b_out  (HMMA)
    split_bf16<<<((size_t)M_ * D_) / 1024, 256>>>(attn, ah, al);
    split_bf16<<<((size_t)D_ * D_) / 1024, 256>>>(w_out, wh, wl);
    gemm_hmma<<<dim3(D_ / 128, M_ / 128), 256, GEMM_SMEM_BYTES>>>(
        ah, al, wh, wl, b_out, out, M_, D_, D_);
}

// round 7
// speedup vs baseline: 3.0979x; 1.6325x over previous
#include <cuda_runtime.h>
#include <cuda_bf16.h>
#include <cstdint>
#include <math.h>

// Problem constants (fixed shapes)
#define B_   2
#define T_   2048
#define D_   2048
#define H_   16
#define HD_  128
#define M_   (B_ * T_)      // 4096 rows
#define N1_  (3 * D_)       // 6144 qkv cols
#define SCALE_ 0.022097086912079612f   // 2048^-0.5  (D, not head_dim!)

// ---------------------------------------------------------------------------
// Scratch (device globals — no allocation allowed)
// ---------------------------------------------------------------------------
__device__ float g_qkv[(size_t)M_ * N1_];          // 100.7 MB
// bf16 split operands
__device__ __nv_bfloat16 g_xh[(size_t)M_ * D_];
__device__ __nv_bfloat16 g_xl[(size_t)M_ * D_];
__device__ __nv_bfloat16 g_wqh[(size_t)N1_ * D_];
__device__ __nv_bfloat16 g_wql[(size_t)N1_ * D_];
__device__ __nv_bfloat16 g_ah[(size_t)M_ * D_];
__device__ __nv_bfloat16 g_al[(size_t)M_ * D_];
__device__ __nv_bfloat16 g_wh[(size_t)D_ * D_];
__device__ __nv_bfloat16 g_wl[(size_t)D_ * D_];
// roped q/k and v, bf16 hi/lo, layout [bh][t][hd]
#define QKV_ELEMS ((size_t)B_ * H_ * T_ * HD_)
__device__ __nv_bfloat16 g_qh[QKV_ELEMS];
__device__ __nv_bfloat16 g_ql[QKV_ELEMS];
__device__ __nv_bfloat16 g_kh[QKV_ELEMS];
__device__ __nv_bfloat16 g_kl[QKV_ELEMS];
__device__ __nv_bfloat16 g_vh[QKV_ELEMS];
__device__ __nv_bfloat16 g_vl[QKV_ELEMS];

// ---------------------------------------------------------------------------
// PTX helpers (family-portable: ldmatrix / mma.sync / cp.async)
// ---------------------------------------------------------------------------
__device__ __forceinline__ uint32_t smem_to_u32(const void* p) {
    uint32_t a;
    asm("{ .reg .u64 t; cvta.to.shared.u64 t, %1; cvt.u32.u64 %0, t; }"
        : "=r"(a) : "l"(p));
    return a;
}
#define SMEM_SWIZZLE_128B(off) ((off) ^ (((off) >> 3) & 0x70))

#define CP_ASYNC16(dst, src) \
    asm volatile("cp.async.cg.shared.global [%0], [%1], 16;" \
                 :: "r"((uint32_t)(dst)), "l"(src))
#define CP_ASYNC_COMMIT() asm volatile("cp.async.commit_group;" ::: "memory")

__device__ __forceinline__ void ldsm4(uint32_t* r, uint32_t addr) {
    asm volatile("ldmatrix.sync.aligned.m8n8.x4.shared.b16 {%0,%1,%2,%3}, [%4];"
                 : "=r"(r[0]), "=r"(r[1]), "=r"(r[2]), "=r"(r[3]) : "r"(addr));
}
__device__ __forceinline__ void ldsm4t(uint32_t* r, uint32_t addr) {
    asm volatile("ldmatrix.sync.aligned.m8n8.x4.trans.shared.b16 {%0,%1,%2,%3}, [%4];"
                 : "=r"(r[0]), "=r"(r[1]), "=r"(r[2]), "=r"(r[3]) : "r"(addr));
}

__device__ __forceinline__ void mma16816(float* c, const uint32_t* a,
                                         uint32_t b0, uint32_t b1) {
    asm volatile(
        "mma.sync.aligned.m16n8k16.row.col.f32.bf16.bf16.f32 "
        "{%0,%1,%2,%3}, {%4,%5,%6,%7}, {%8,%9}, {%0,%1,%2,%3};"
        : "+f"(c[0]), "+f"(c[1]), "+f"(c[2]), "+f"(c[3])
        : "r"(a[0]), "r"(a[1]), "r"(a[2]), "r"(a[3]), "r"(b0), "r"(b1));
}

__device__ __forceinline__ void pack_hl(float p0, float p1,
                                        uint32_t& h, uint32_t& l) {
    __nv_bfloat162 hh = __floats2bfloat162_rn(p0, p1);
    float r0 = p0 - __bfloat162float(hh.x);
    float r1 = p1 - __bfloat162float(hh.y);
    __nv_bfloat162 ll = __floats2bfloat162_rn(r0, r1);
    h = *(uint32_t*)&hh;
    l = *(uint32_t*)&ll;
}

// ---------------------------------------------------------------------------
// fp32 -> (bf16 hi, bf16 lo) split, vectorized
// ---------------------------------------------------------------------------
__global__ __launch_bounds__(256) void split_bf16(
    const float* __restrict__ src, __nv_bfloat16* __restrict__ hi,
    __nv_bfloat16* __restrict__ lo)
{
    const int i = blockIdx.x * 256 + threadIdx.x;   // float4 index
    float4 v = ((const float4*)src)[i];
    uint32_t h0, l0, h1, l1;
    pack_hl(v.x, v.y, h0, l0);
    pack_hl(v.z, v.w, h1, l1);
    ((uint2*)hi)[i] = make_uint2(h0, h1);
    ((uint2*)lo)[i] = make_uint2(l0, l1);
}

// ---------------------------------------------------------------------------
// HMMA GEMM: C[M,N] = A[M,K] @ W[N,K]^T + bias   (bf16 3-term split)
// (unchanged from R6 passing version)
// ---------------------------------------------------------------------------
#define GEMM_SMEM_BYTES (131072 + 1024)

__device__ __forceinline__ void load_chunk(
    const __nv_bfloat16* Ah, const __nv_bfloat16* Al,
    const __nv_bfloat16* Bh, const __nv_bfloat16* Bl,
    int bm, int bn, int K, int k0, uint32_t dbase, int tid)
{
#pragma unroll
    for (int i = 0; i < 16; i++) {
        const int idx = tid + i * 256;
        const int t   = idx >> 10;
        const int r   = (idx >> 3) & 127;
        const int c16 = idx & 7;
        const __nv_bfloat16* sp;
        int row;
        if (t == 0)      { sp = Ah; row = bm + r; }
        else if (t == 1) { sp = Al; row = bm + r; }
        else if (t == 2) { sp = Bh; row = bn + r; }
        else             { sp = Bl; row = bn + r; }
        const char* src = (const char*)sp +
            (((size_t)row * K + k0) << 1) + (c16 << 4);
        const uint32_t off = (r << 7) + (c16 << 4);
        const uint32_t dst = dbase + (t << 14) + SMEM_SWIZZLE_128B(off);
        CP_ASYNC16(dst, src);
    }
    CP_ASYNC_COMMIT();
}

__global__ __launch_bounds__(256, 1) void gemm_hmma(
    const __nv_bfloat16* __restrict__ Ah, const __nv_bfloat16* __restrict__ Al,
    const __nv_bfloat16* __restrict__ Bh, const __nv_bfloat16* __restrict__ Bl,
    const float* __restrict__ bias, float* __restrict__ C,
    int M, int N, int K)
{
    extern __shared__ __align__(16) char smem[];
    const uint32_t data0 = (smem_to_u32(smem) + 1023) & ~1023u;

    const int tid  = threadIdx.x;
    const int lane = tid & 31;
    const int wid  = tid >> 5;
    const int warp_m = wid >> 2;
    const int warp_n = wid & 3;
    const int bm = blockIdx.y * 128;
    const int bn = blockIdx.x * 128;

    const uint32_t a_row = warp_m * 64 + (lane & 15);
    const uint32_t a_kb  = (uint32_t)(lane >> 4) << 4;
    const uint32_t b_row = warp_n * 32 + (lane & 7) + (((uint32_t)lane >> 4) << 3);
    const uint32_t b_kb  = (((uint32_t)lane >> 3) & 1) << 4;

    float acc[4][4][4];
#pragma unroll
    for (int mt = 0; mt < 4; mt++)
#pragma unroll
        for (int nt = 0; nt < 4; nt++)
#pragma unroll
            for (int r = 0; r < 4; r++) acc[mt][nt][r] = 0.0f;

    const int nchunks = K >> 6;
    load_chunk(Ah, Al, Bh, Bl, bm, bn, K, 0, data0, tid);

    for (int c = 0; c < nchunks; c++) {
        if (c + 1 < nchunks) {
            load_chunk(Ah, Al, Bh, Bl, bm, bn, K, (c + 1) << 6,
                       data0 + ((c + 1) & 1) * 65536, tid);
            asm volatile("cp.async.wait_group 1;" ::: "memory");
        } else {
            asm volatile("cp.async.wait_group 0;" ::: "memory");
        }
        __syncthreads();

        const uint32_t dbase = data0 + (c & 1) * 65536;
        const uint32_t sAh = dbase;
        const uint32_t sAl = dbase + 16384;
        const uint32_t sBh = dbase + 32768;
        const uint32_t sBl = dbase + 49152;

#pragma unroll
        for (int ks = 0; ks < 4; ks++) {
            const uint32_t kbyte = (uint32_t)ks << 5;

            uint32_t af_h[4][4], af_l[4][4];
#pragma unroll
            for (int mt = 0; mt < 4; mt++) {
                const uint32_t off = ((a_row + mt * 16) << 7) + kbyte + a_kb;
                const uint32_t sw = SMEM_SWIZZLE_128B(off);
                ldsm4(af_h[mt], sAh + sw);
                ldsm4(af_l[mt], sAl + sw);
            }
            uint32_t bf_h[2][4], bf_l[2][4];
#pragma unroll
            for (int ng = 0; ng < 2; ng++) {
                const uint32_t off = ((b_row + ng * 16) << 7) + kbyte + b_kb;
                const uint32_t sw = SMEM_SWIZZLE_128B(off);
                ldsm4(bf_h[ng], sBh + sw);
                ldsm4(bf_l[ng], sBl + sw);
            }
#pragma unroll
            for (int mt = 0; mt < 4; mt++) {
#pragma unroll
                for (int nt = 0; nt < 4; nt++) {
                    const int ng = nt >> 1, lo = (nt & 1) * 2;
                    mma16816(acc[mt][nt], af_h[mt], bf_h[ng][lo], bf_h[ng][lo + 1]);
                    mma16816(acc[mt][nt], af_h[mt], bf_l[ng][lo], bf_l[ng][lo + 1]);
                    mma16816(acc[mt][nt], af_l[mt], bf_h[ng][lo], bf_h[ng][lo + 1]);
                }
            }
        }
        __syncthreads();
    }

    const int gm0 = bm + warp_m * 64 + (lane >> 2);
    const int gn0 = bn + warp_n * 32 + (lane & 3) * 2;
#pragma unroll
    for (int mt = 0; mt < 4; mt++) {
#pragma unroll
        for (int nt = 0; nt < 4; nt++) {
            const int gm = gm0 + mt * 16;
            const int gn = gn0 + nt * 8;
            const float b0 = bias[gn], b1 = bias[gn + 1];
            float2 v0 = make_float2(acc[mt][nt][0] + b0, acc[mt][nt][1] + b1);
            float2 v1 = make_float2(acc[mt][nt][2] + b0, acc[mt][nt][3] + b1);
            *(float2*)&C[(size_t)gm * N + gn]       = v0;
            *(float2*)&C[(size_t)(gm + 8) * N + gn] = v1;
        }
    }
}

// ---------------------------------------------------------------------------
// RoPE + split qkv -> q/k/v bf16 hi/lo, layout [bh][t][hd]
// ---------------------------------------------------------------------------
__device__ __forceinline__ void st_hl(float v, __nv_bfloat16* hi,
                                      __nv_bfloat16* lo, size_t idx) {
    __nv_bfloat16 h = __float2bfloat16(v);
    hi[idx] = h;
    lo[idx] = __float2bfloat16(v - __bfloat162float(h));
}

__global__ __launch_bounds__(256) void rope_split_hl(
    const float* __restrict__ qkv,
    __nv_bfloat16* __restrict__ qh, __nv_bfloat16* __restrict__ ql,
    __nv_bfloat16* __restrict__ kh, __nv_bfloat16* __restrict__ kl,
    __nv_bfloat16* __restrict__ vh, __nv_bfloat16* __restrict__ vl)
{
    const int idx = blockIdx.x * blockDim.x + threadIdx.x;
    const int i  = idx & 63;
    const int t  = (idx >> 6) & (T_ - 1);
    const int h  = (idx >> 17) & (H_ - 1);
    const int b  = idx >> 21;
    const int bh = idx >> 17;

    const float* src = qkv + ((size_t)(b * T_ + t)) * N1_ + h * (3 * HD_);
    const float q1 = src[i],        q2 = src[64 + i];
    const float k1 = src[128 + i],  k2 = src[192 + i];
    const float v1 = src[256 + i],  v2 = src[320 + i];

    const float theta = powf(10000.0f, -(float)i * (1.0f / 64.0f));
    const float ang = (float)t * theta;
    const float cs = cosf(ang), sn = sinf(ang);

    const size_t dst = ((size_t)bh * T_ + t) * HD_ + i;
    st_hl(q1 * cs - q2 * sn, qh, ql, dst);
    st_hl(q1 * sn + q2 * cs, qh, ql, dst + 64);
    st_hl(k1 * cs - k2 * sn, kh, kl, dst);
    st_hl(k1 * sn + k2 * cs, kh, kl, dst + 64);
    st_hl(v1, vh, vl, dst);
    st_hl(v2, vh, vl, dst + 64);
}

// ---------------------------------------------------------------------------
// Causal flash attention on mma.sync bf16 (3-term splits).
// CTA: 128 q-rows x Bc=64 kv, 8 warps x 16 q-rows.
// SMEM (272B padded rows, no swizzle — conflict-free for ldmatrix):
//   Qh 34816 | Ql 34816 | 2 x { Kh, Kl, Vh, Vl : 17408 each } = 208896 B
// Output written directly as bf16 hi/lo into g_ah/g_al ([B*T][D] layout).
// ---------------------------------------------------------------------------
#define FL_SMEM_BYTES 208896
#define FL_STRIDE 272

__device__ __forceinline__ void fl_load_kv(
    const __nv_bfloat16* Kh, const __nv_bfloat16* Kl,
    const __nv_bfloat16* Vh, const __nv_bfloat16* Vl,
    size_t goff, uint32_t sbuf, int tid)
{
#pragma unroll
    for (int i = 0; i < 16; i++) {
        const int idx = tid + i * 256;
        const int arr = idx >> 10;          // 0:Kh 1:Kl 2:Vh 3:Vl
        const int r   = (idx >> 4) & 63;
        const int seg = idx & 15;
        const __nv_bfloat16* p = (arr == 0) ? Kh : (arr == 1) ? Kl
                               : (arr == 2) ? Vh : Vl;
        const char* src = (const char*)p + ((goff + (size_t)r * HD_) << 1) + (seg << 4);
        const uint32_t dst = sbuf + arr * 17408 + r * FL_STRIDE + (seg << 4);
        CP_ASYNC16(dst, src);
    }
    CP_ASYNC_COMMIT();
}

__global__ __launch_bounds__(256, 1) void flash_hmma(
    const __nv_bfloat16* __restrict__ Qh, const __nv_bfloat16* __restrict__ Ql,
    const __nv_bfloat16* __restrict__ Kh, const __nv_bfloat16* __restrict__ Kl,
    const __nv_bfloat16* __restrict__ Vh, const __nv_bfloat16* __restrict__ Vl,
    __nv_bfloat16* __restrict__ Oh, __nv_bfloat16* __restrict__ Ol)
{
    extern __shared__ __align__(16) char smc[];
    const uint32_t sb  = smem_to_u32(smc);
    const uint32_t sQh = sb, sQl = sb + 34816;
    const uint32_t sKV = sb + 69632;            // + buf*69632

    const int tid  = threadIdx.x;
    const int lane = tid & 31;
    const int warp = tid >> 5;
    const int qt = 15 - (int)blockIdx.x;        // heavy blocks first
    const int bh = blockIdx.y;
    const int b = bh >> 4, h = bh & 15;
    const size_t gbase = (size_t)bh * T_ * HD_;

    // Q load (hi + lo)
    {
        const size_t qoff = gbase + (size_t)qt * 128 * HD_;
#pragma unroll
        for (int i = 0; i < 16; i++) {
            const int idx = tid + i * 256;
            const int arr = idx >> 11;
            const int r   = (idx >> 4) & 127;
            const int seg = idx & 15;
            const char* src = (const char*)(arr ? Ql : Qh) +
                ((qoff + (size_t)r * HD_) << 1) + (seg << 4);
            const uint32_t dst = (arr ? sQl : sQh) + r * FL_STRIDE + (seg << 4);
            CP_ASYNC16(dst, src);
        }
        CP_ASYNC_COMMIT();
    }
    // first KV tile
    fl_load_kv(Kh, Kl, Vh, Vl, gbase, sKV, tid);

    // per-warp fragment address bases
    const int r0w = warp * 16;
    const uint32_t aoff = (r0w + (lane & 15)) * FL_STRIDE + ((lane >> 4) << 4);
    const uint32_t boff = ((lane & 7) + ((lane >> 4) << 3)) * FL_STRIDE +
                          (((lane >> 3) & 1) << 4);
    const uint32_t vrow = (lane & 7) + (((lane >> 3) & 1) << 3);
    const uint32_t vcol = (lane >> 4) << 4;

    float o[16][4];
#pragma unroll
    for (int nt = 0; nt < 16; nt++)
#pragma unroll
        for (int r = 0; r < 4; r++) o[nt][r] = 0.0f;
    float m_[2] = {-1e30f, -1e30f};
    float l_[2] = {0.0f, 0.0f};

    const int ktmax = 2 * qt + 1;
    for (int kt = 0; kt <= ktmax; kt++) {
        if (kt > 0) __syncthreads();   // all done reading buf being prefetched into
        if (kt < ktmax) {
            fl_load_kv(Kh, Kl, Vh, Vl, gbase + (size_t)(kt + 1) * 64 * HD_,
                       sKV + ((kt + 1) & 1) * 69632, tid);
            asm volatile("cp.async.wait_group 1;" ::: "memory");
        } else {
            asm volatile("cp.async.wait_group 0;" ::: "memory");
        }
        __syncthreads();

        const uint32_t kb = sKV + (kt & 1) * 69632;
        const uint32_t sKh = kb, sKl = kb + 17408;
        const uint32_t sVh = kb + 34816, sVl = kb + 52224;

        // ---- S = Q K^T (3-term) ----
        float s[8][4];
#pragma unroll
        for (int nt = 0; nt < 8; nt++)
#pragma unroll
            for (int r = 0; r < 4; r++) s[nt][r] = 0.0f;

#pragma unroll
        for (int ks = 0; ks < 8; ks++) {
            const uint32_t kbyte = (uint32_t)ks << 5;
            uint32_t ah_[4], al_[4];
            ldsm4(ah_, sQh + aoff + kbyte);
            ldsm4(al_, sQl + aoff + kbyte);
            uint32_t bh_[4][4], bl_[4][4];
#pragma unroll
            for (int np = 0; np < 4; np++) {
                const uint32_t off = boff + np * 16 * FL_STRIDE + kbyte;
                ldsm4(bh_[np], sKh + off);
                ldsm4(bl_[np], sKl + off);
            }
#pragma unroll
            for (int nt = 0; nt < 8; nt++) {
                const int ng = nt >> 1, lo = (nt & 1) * 2;
                mma16816(s[nt], ah_, bh_[ng][lo], bh_[ng][lo + 1]);
                mma16816(s[nt], ah_, bl_[ng][lo], bl_[ng][lo + 1]);
                mma16816(s[nt], al_, bh_[ng][lo], bh_[ng][lo + 1]);
            }
        }

        // ---- scale + mask + online softmax ----
        const int qa = qt * 128 + r0w + (lane >> 2);
        const int qb = qa + 8;
        const bool dg = (kt >= 2 * qt);
#pragma unroll
        for (int nt = 0; nt < 8; nt++) {
            const int c0 = kt * 64 + nt * 8 + (lane & 3) * 2;
            s[nt][0] *= SCALE_; s[nt][1] *= SCALE_;
            s[nt][2] *= SCALE_; s[nt][3] *= SCALE_;
            if (dg) {
                if (c0     > qa) s[nt][0] = -1e30f;
                if (c0 + 1 > qa) s[nt][1] = -1e30f;
                if (c0     > qb) s[nt][2] = -1e30f;
                if (c0 + 1 > qb) s[nt][3] = -1e30f;
            }
        }
        float ma = -1e30f, mb = -1e30f;
#pragma unroll
        for (int nt = 0; nt < 8; nt++) {
            ma = fmaxf(ma, fmaxf(s[nt][0], s[nt][1]));
            mb = fmaxf(mb, fmaxf(s[nt][2], s[nt][3]));
        }
        ma = fmaxf(ma, __shfl_xor_sync(0xFFFFFFFF, ma, 1));
        ma = fmaxf(ma, __shfl_xor_sync(0xFFFFFFFF, ma, 2));
        mb = fmaxf(mb, __shfl_xor_sync(0xFFFFFFFF, mb, 1));
        mb = fmaxf(mb, __shfl_xor_sync(0xFFFFFFFF, mb, 2));
        const float mna = fmaxf(m_[0], ma), mnb = fmaxf(m_[1], mb);
        const float ca = __expf(m_[0] - mna), cb = __expf(m_[1] - mnb);
        float suma = 0.0f, sumb = 0.0f;
#pragma unroll
        for (int nt = 0; nt < 8; nt++) {
            s[nt][0] = __expf(s[nt][0] - mna); suma += s[nt][0];
            s[nt][1] = __expf(s[nt][1] - mna); suma += s[nt][1];
            s[nt][2] = __expf(s[nt][2] - mnb); sumb += s[nt][2];
            s[nt][3] = __expf(s[nt][3] - mnb); sumb += s[nt][3];
        }
        suma += __shfl_xor_sync(0xFFFFFFFF, suma, 1);
        suma += __shfl_xor_sync(0xFFFFFFFF, suma, 2);
        sumb += __shfl_xor_sync(0xFFFFFFFF, sumb, 1);
        sumb += __shfl_xor_sync(0xFFFFFFFF, sumb, 2);
        l_[0] = l_[0] * ca + suma;  m_[0] = mna;
        l_[1] = l_[1] * cb + sumb;  m_[1] = mnb;
#pragma unroll
        for (int nt = 0; nt < 16; nt++) {
            o[nt][0] *= ca; o[nt][1] *= ca;
            o[nt][2] *= cb; o[nt][3] *= cb;
        }

        // ---- P fragments (bf16 hi/lo) ----
        uint32_t pa_h[4][4], pa_l[4][4];
#pragma unroll
        for (int j = 0; j < 4; j++) {
            pack_hl(s[2 * j][0],     s[2 * j][1],     pa_h[j][0], pa_l[j][0]);
            pack_hl(s[2 * j][2],     s[2 * j][3],     pa_h[j][1], pa_l[j][1]);
            pack_hl(s[2 * j + 1][0], s[2 * j + 1][1], pa_h[j][2], pa_l[j][2]);
            pack_hl(s[2 * j + 1][2], s[2 * j + 1][3], pa_h[j][3], pa_l[j][3]);
        }

        // ---- O += P V (3-term), V via ldmatrix.trans ----
#pragma unroll
        for (int j = 0; j < 4; j++) {
            const uint32_t rbase = (j * 16 + vrow) * FL_STRIDE + vcol;
#pragma unroll
            for (int dp = 0; dp < 8; dp++) {
                uint32_t vh_[4], vl_[4];
                const uint32_t off = rbase + dp * 32;
                ldsm4t(vh_, sVh + off);
                ldsm4t(vl_, sVl + off);
                const int nt0 = dp * 2, nt1 = nt0 + 1;
                mma16816(o[nt0], pa_h[j], vh_[0], vh_[1]);
                mma16816(o[nt0], pa_l[j], vh_[0], vh_[1]);
                mma16816(o[nt0], pa_h[j], vl_[0], vl_[1]);
                mma16816(o[nt1], pa_h[j], vh_[2], vh_[3]);
                mma16816(o[nt1], pa_l[j], vh_[2], vh_[3]);
                mma16816(o[nt1], pa_h[j], vl_[2], vl_[3]);
            }
        }
    }

    // ---- epilogue: normalize, write bf16 hi/lo to [B*T][D] ----
    const float inva = 1.0f / l_[0], invb = 1.0f / l_[1];
    const int ta = qt * 128 + r0w + (lane >> 2);
    const size_t rowa = (size_t)(b * T_ + ta) * D_;
    const size_t rowb = rowa + 8 * D_;
    const int cb0 = h * HD_ + (lane & 3) * 2;
#pragma unroll
    for (int nt = 0; nt < 16; nt++) {
        const size_t ia = rowa + cb0 + nt * 8;
        const size_t ib = rowb + cb0 + nt * 8;
        uint32_t hA, lA, hB, lB;
        pack_hl(o[nt][0] * inva, o[nt][1] * inva, hA, lA);
        pack_hl(o[nt][2] * invb, o[nt][3] * invb, hB, lB);
        *(uint32_t*)(Oh + ia) = hA;  *(uint32_t*)(Ol + ia) = lA;
        *(uint32_t*)(Oh + ib) = hB;  *(uint32_t*)(Ol + ib) = lB;
    }
}

// ---------------------------------------------------------------------------
// kernel_launch
// ---------------------------------------------------------------------------
extern "C" void kernel_launch(void* const* d_in, const int* in_sizes, int n_in,
                              void* d_out, int out_size)
{
    const float* x     = (const float*)d_in[0];
    const float* w_qkv = (const float*)d_in[1];
    const float* b_qkv = (const float*)d_in[2];
    const float* w_out = (const float*)d_in[3];
    const float* b_out = (const float*)d_in[4];
    float* out = (float*)d_out;

    float* qkv;
    cudaGetSymbolAddress((void**)&qkv, g_qkv);
    __nv_bfloat16 *xh, *xl, *wqh, *wql, *ah, *al, *wh, *wl;
    __nv_bfloat16 *qh, *ql, *kh, *kl, *vh, *vl;
    cudaGetSymbolAddress((void**)&xh,  g_xh);
    cudaGetSymbolAddress((void**)&xl,  g_xl);
    cudaGetSymbolAddress((void**)&wqh, g_wqh);
    cudaGetSymbolAddress((void**)&wql, g_wql);
    cudaGetSymbolAddress((void**)&ah,  g_ah);
    cudaGetSymbolAddress((void**)&al,  g_al);
    cudaGetSymbolAddress((void**)&wh,  g_wh);
    cudaGetSymbolAddress((void**)&wl,  g_wl);
    cudaGetSymbolAddress((void**)&qh,  g_qh);
    cudaGetSymbolAddress((void**)&ql,  g_ql);
    cudaGetSymbolAddress((void**)&kh,  g_kh);
    cudaGetSymbolAddress((void**)&kl,  g_kl);
    cudaGetSymbolAddress((void**)&vh,  g_vh);
    cudaGetSymbolAddress((void**)&vl,  g_vl);

    cudaFuncSetAttribute(gemm_hmma,
                         cudaFuncAttributeMaxDynamicSharedMemorySize,
                         GEMM_SMEM_BYTES);
    cudaFuncSetAttribute(flash_hmma,
                         cudaFuncAttributeMaxDynamicSharedMemorySize,
                         FL_SMEM_BYTES);

    // 0) split x / w_qkv into bf16 hi/lo
    split_bf16<<<((size_t)M_ * D_) / 1024, 256>>>(x, xh, xl);
    split_bf16<<<((size_t)N1_ * D_) / 1024, 256>>>(w_qkv, wqh, wql);
    // 1) qkv = x @ w_qkv^T + b_qkv   (HMMA)
    gemm_hmma<<<dim3(N1_ / 128, M_ / 128), 256, GEMM_SMEM_BYTES>>>(
        xh, xl, wqh, wql, b_qkv, qkv, M_, N1_, D_);
    // 2) RoPE + head split -> bf16 hi/lo
    rope_split_hl<<<(B_ * H_ * T_ * 64) / 256, 256>>>(qkv, qh, ql, kh, kl, vh, vl);
    // 3) causal flash attention (HMMA) -> attn bf16 hi/lo directly
    flash_hmma<<<dim3(16, B_ * H_), 256, FL_SMEM_BYTES>>>(
        qh, ql, kh, kl, vh, vl, ah, al);
    // 4) out = attn @ w_out^T + b_out  (HMMA)
    split_bf16<<<((size_t)D_ * D_) / 1024, 256>>>(w_out, wh, wl);
    gemm_hmma<<<dim3(D_ / 128, M_ / 128), 256, GEMM_SMEM_BYTES>>>(
        ah, al, wh, wl, b_out, out, M_, D_, D_);
}